// round 11
// baseline (speedup 1.0000x reference)
#include <cuda_runtime.h>
#include <cuda_bf16.h>
#include <cuda_fp16.h>
#include <math_constants.h>
#include <cstdint>

#define D      256
#define K      1024
#define NROWS  65536
#define GM     128          // rows per gemm block
#define CAP    16
#define MARGIN 3.0e-3f

__device__ float  g_cnorm[K];
__device__ double g_loss_sum;
__device__ __nv_bfloat16 g_cbf[K * D];       // bf16 codebook
__device__ unsigned short g_cand[NROWS * CAP];
__device__ int    g_ccnt[NROWS];

// ---------------------------------------------------------------------------
__device__ __forceinline__ void mma16816(float* c, const unsigned* a,
                                         unsigned b0, unsigned b1){
    asm volatile("mma.sync.aligned.m16n8k16.row.col.f32.bf16.bf16.f32 "
        "{%0,%1,%2,%3}, {%4,%5,%6,%7}, {%8,%9}, {%0,%1,%2,%3};"
        : "+f"(c[0]), "+f"(c[1]), "+f"(c[2]), "+f"(c[3])
        : "r"(a[0]), "r"(a[1]), "r"(a[2]), "r"(a[3]), "r"(b0), "r"(b1));
}

#define LDSM4(r, ad)                                                         \
    asm volatile("ldmatrix.sync.aligned.m8n8.x4.shared.b16 {%0,%1,%2,%3}, [%4];" \
        : "=r"((r)[0]), "=r"((r)[1]), "=r"((r)[2]), "=r"((r)[3]) : "r"(ad))

__device__ __forceinline__ uint32_t s2u(const void* p){
    uint32_t a;
    asm("{ .reg .u64 t; cvta.to.shared.u64 t, %1; cvt.u32.u64 %0, t; }" : "=r"(a) : "l"(p));
    return a;
}

// smem layout (bytes)
#define OFF_A   0          // 65536: A as [kb(4)][row(128)][128B], 16B-unit XOR swizzle
#define OFF_B   65536      // 32768: 4 bufs x (64 codes x 128B), same swizzle
#define OFF_CN  98304      // 4096
#define OFF_CNT 102400     // 512
#define GSMEM   102912

// ---------------------------------------------------------------------------
// Kernel 1: codebook norms (bit-exact) + cb->bf16 + zero loss. grid 128 x 256.
// ---------------------------------------------------------------------------
__global__ void k_setup(const float* __restrict__ cb){
    if (blockIdx.x == 0 && threadIdx.x == 0) g_loss_sum = 0.0;
    int w    = threadIdx.x >> 5;
    int lane = threadIdx.x & 31;
    int code = blockIdx.x * 8 + w;
    const float* c = cb + (size_t)code * D;
    float s = 0.f;
    #pragma unroll
    for (int j = 0; j < 8; j++){
        float v = c[lane + 32 * j];
        s = __fmaf_rn(v, v, s);
    }
    #pragma unroll
    for (int off = 16; off; off >>= 1)
        s += __shfl_xor_sync(0xffffffffu, s, off);
    if (lane == 0) g_cnorm[code] = s;

    int g = blockIdx.x * 256 + threadIdx.x;
    const float4* cb4 = (const float4*)cb;
    float4 x = cb4[g * 2], y = cb4[g * 2 + 1];
    __nv_bfloat162 p0 = __floats2bfloat162_rn(x.x, x.y);
    __nv_bfloat162 p1 = __floats2bfloat162_rn(x.z, x.w);
    __nv_bfloat162 p2 = __floats2bfloat162_rn(y.x, y.y);
    __nv_bfloat162 p3 = __floats2bfloat162_rn(y.z, y.w);
    uint4 o;
    o.x = *(unsigned*)&p0; o.y = *(unsigned*)&p1;
    o.z = *(unsigned*)&p2; o.w = *(unsigned*)&p3;
    ((uint4*)g_cbf)[g] = o;
}

// ---------------------------------------------------------------------------
// Kernel 2: HMMA bf16 GEMM. Warp tile 16 rows x 64 codes (acc = 32 regs, no
// spills under the 128-reg cap). 16 code tiles of 64, 4 k-chunks each ->
// 64 chunks of 8 KB, 4-deep cp.async ring (wait_group 2, prefetch 3 ahead).
// Register-resident running min + warp-local streaming candidate emission.
// ---------------------------------------------------------------------------
__global__ __launch_bounds__(256, 2) void k_gemm(const float* __restrict__ Z){
    extern __shared__ __align__(16) unsigned char smraw[];
    float* cn   = (float*)(smraw + OFF_CN);
    int*   scnt = (int*)(smraw + OFF_CNT);
    const uint32_t smem = s2u(smraw);

    const int tid  = threadIdx.x;
    const int l    = tid & 31;
    const int w    = tid >> 5;
    const int gid  = l >> 2;
    const int tig  = l & 3;
    const int row0 = blockIdx.x * GM;
    const int wr0  = w * 16;

    // --- A: load f32, convert bf16, store swizzled: [kb][row][unit^(row&7)] ---
    {
        const float4* Z4 = (const float4*)(Z + (size_t)row0 * D);
        #pragma unroll
        for (int j = 0; j < 16; j++){
            int i = tid + 256 * j;          // 0..4095 : 16B units
            int r = i >> 5;                 // row 0..127
            int u = i & 31;                 // k-unit 0..31 (k = u*8)
            int kb = u >> 3, uu = u & 7;
            float4 v0 = Z4[r * 64 + u * 2];
            float4 v1 = Z4[r * 64 + u * 2 + 1];
            __nv_bfloat162 p0 = __floats2bfloat162_rn(v0.x, v0.y);
            __nv_bfloat162 p1 = __floats2bfloat162_rn(v0.z, v0.w);
            __nv_bfloat162 p2 = __floats2bfloat162_rn(v1.x, v1.y);
            __nv_bfloat162 p3 = __floats2bfloat162_rn(v1.z, v1.w);
            uint4 o;
            o.x = *(unsigned*)&p0; o.y = *(unsigned*)&p1;
            o.z = *(unsigned*)&p2; o.w = *(unsigned*)&p3;
            *(uint4*)(smraw + OFF_A + (kb * 128 + r) * 128
                      + ((uu ^ (r & 7)) << 4)) = o;
        }
    }
    #pragma unroll
    for (int j = 0; j < 4; j++) cn[tid + 256 * j] = g_cnorm[tid + 256 * j];
    if (tid < GM) scnt[tid] = 0;

    // --- B chunk loader: cc in 0..63, ct = cc>>2 (64-code tile), kc = cc&3 ---
    auto issueB = [&](int cc){
        int ct = cc >> 2, kc = cc & 3;
        uint32_t dstb = smem + OFF_B + (uint32_t)((cc & 3) << 13);
        #pragma unroll
        for (int j = 0; j < 2; j++){
            int i    = tid + 256 * j;       // 0..511 16B units
            int code = i >> 3;              // 0..63
            int uu   = i & 7;
            uint32_t dst = dstb + (uint32_t)(code * 128 + ((uu ^ (code & 7)) << 4));
            const void* src = g_cbf + (size_t)(ct * 64 + code) * D + kc * 64 + uu * 8;
            asm volatile("cp.async.cg.shared.global [%0], [%1], 16;"
                         :: "r"(dst), "l"(src) : "memory");
        }
        asm volatile("cp.async.commit_group;" ::: "memory");
    };

    // --- ldmatrix per-thread address components (validated round-8 layout) ---
    const int arow  = wr0 + (l & 15);
    const int asel  = l >> 4;
    const uint32_t abase = smem + OFF_A + (uint32_t)(arow * 128);
    const int ax = arow & 7;
    const int bno  = (l & 7) + ((l & 16) ? 8 : 0);
    const int bsel = (l >> 3) & 1;
    const uint32_t bbase = smem + OFF_B + (uint32_t)(bno * 128);
    const int bx = bno & 7;

    issueB(0); issueB(1); issueB(2);      // prefill 3 deep

    float acc[8][4];
    float rm_lo = CUDART_INF_F, rm_hi = CUDART_INF_F;

    for (int cc = 0; cc < 64; cc++){
        const int kc = cc & 3;
        const int ct = cc >> 2;

        asm volatile("cp.async.wait_group 2;" ::: "memory");  // chunk cc arrived
        __syncthreads();      // publish buf(cc); compute(cc-1) done by all
        if (cc + 3 < 64) issueB(cc + 3);  // overwrites buf (cc-1)&3 (now free)

        if (kc == 0){
            #pragma unroll
            for (int n = 0; n < 8; n++)
                #pragma unroll
                for (int q = 0; q < 4; q++) acc[n][q] = 0.f;
        }

        const uint32_t bufb = bbase + (uint32_t)((cc & 3) << 13);
        #pragma unroll
        for (int ks = 0; ks < 4; ks++){
            unsigned a[4];
            LDSM4(a, abase + (uint32_t)((kc << 14)
                   + ((((ks << 1) + asel) ^ ax) << 4)));
            #pragma unroll
            for (int n4 = 0; n4 < 4; n4++){
                unsigned b[4];
                LDSM4(b, bufb + (uint32_t)(n4 * 2048
                       + ((((ks << 1) + bsel) ^ bx) << 4)));
                mma16816(acc[2 * n4],     a, b[0], b[1]);
                mma16816(acc[2 * n4 + 1], a, b[2], b[3]);
            }
        }

        if (kc == 3){
            // ---- warp-local epilogue for 64-code tile ct ----
            float mnlo = CUDART_INF_F, mnhi = CUDART_INF_F;
            #pragma unroll
            for (int n = 0; n < 8; n++){
                int col = ct * 64 + n * 8 + 2 * tig;
                float c0 = cn[col], c1 = cn[col + 1];
                mnlo = fminf(mnlo, fminf(__fmaf_rn(-2.f, acc[n][0], c0),
                                         __fmaf_rn(-2.f, acc[n][1], c1)));
                mnhi = fminf(mnhi, fminf(__fmaf_rn(-2.f, acc[n][2], c0),
                                         __fmaf_rn(-2.f, acc[n][3], c1)));
            }
            #pragma unroll
            for (int off = 1; off < 4; off <<= 1){
                mnlo = fminf(mnlo, __shfl_xor_sync(0xffffffffu, mnlo, off));
                mnhi = fminf(mnhi, __shfl_xor_sync(0xffffffffu, mnhi, off));
            }
            rm_lo = fminf(rm_lo, mnlo);
            rm_hi = fminf(rm_hi, mnhi);
            const float th_lo = rm_lo + MARGIN;
            const float th_hi = rm_hi + MARGIN;
            const int r_lo = wr0 + gid, r_hi = r_lo + 8;
            #pragma unroll
            for (int n = 0; n < 8; n++){
                int col = ct * 64 + n * 8 + 2 * tig;
                float c0 = cn[col], c1 = cn[col + 1];
                float s0 = __fmaf_rn(-2.f, acc[n][0], c0);
                float s1 = __fmaf_rn(-2.f, acc[n][1], c1);
                float s2 = __fmaf_rn(-2.f, acc[n][2], c0);
                float s3 = __fmaf_rn(-2.f, acc[n][3], c1);
                if (s0 <= th_lo){
                    int p = atomicAdd(&scnt[r_lo], 1);
                    if (p < CAP) g_cand[(size_t)(row0 + r_lo) * CAP + p] = (unsigned short)col;
                }
                if (s1 <= th_lo){
                    int p = atomicAdd(&scnt[r_lo], 1);
                    if (p < CAP) g_cand[(size_t)(row0 + r_lo) * CAP + p] = (unsigned short)(col + 1);
                }
                if (s2 <= th_hi){
                    int p = atomicAdd(&scnt[r_hi], 1);
                    if (p < CAP) g_cand[(size_t)(row0 + r_hi) * CAP + p] = (unsigned short)col;
                }
                if (s3 <= th_hi){
                    int p = atomicAdd(&scnt[r_hi], 1);
                    if (p < CAP) g_cand[(size_t)(row0 + r_hi) * CAP + p] = (unsigned short)(col + 1);
                }
            }
        }
    }
    __syncthreads();
    if (tid < GM) g_ccnt[row0 + tid] = scnt[tid];
}

// ---------------------------------------------------------------------------
// Kernel 3: exact rescore (lanes = candidates) + fused gather/output/loss.
// 1 warp per row. Bit-exact round-0 arithmetic; lexicographic tie-break.
// ---------------------------------------------------------------------------
__global__ __launch_bounds__(256) void k_rescore(
    const float* __restrict__ Z, const float* __restrict__ CB,
    float4* __restrict__ Oz, float* __restrict__ out_idx)
{
    __shared__ float szs[8][256];
    __shared__ float wsum[8];
    const int w    = threadIdx.x >> 5;
    const int lane = threadIdx.x & 31;
    const int row  = blockIdx.x * 8 + w;
    float* zr = szs[w];
    const float4* zr4 = (const float4*)zr;

    const float4* Z4 = (const float4*)(Z + (size_t)row * D);
    #pragma unroll
    for (int j = 0; j < 2; j++)
        *(float4*)(zr + (lane + 32 * j) * 4) = Z4[lane + 32 * j];
    __syncwarp();

    // zn: exact 8-accumulator pairwise-halving tree (bit-match reference)
    int l8 = lane & 7;
    float a = 0.f;
    #pragma unroll
    for (int i = 0; i < 32; i++){
        float x = zr[i * 8 + l8];
        a = __fadd_rn(a, __fmul_rn(x, x));
    }
    float aj  = __shfl_sync(0xffffffffu, a, lane & 3);
    float aj4 = __shfl_sync(0xffffffffu, a, (lane & 3) + 4);
    float b   = __fadd_rn(aj, aj4);
    float b0 = __shfl_sync(0xffffffffu, b, 0);
    float b1 = __shfl_sync(0xffffffffu, b, 1);
    float b2 = __shfl_sync(0xffffffffu, b, 2);
    float b3 = __shfl_sync(0xffffffffu, b, 3);
    float zn = __fadd_rn(__fadd_rn(b0, b2), __fadd_rn(b1, b3));

    const int cnt = g_ccnt[row];
    float bs = CUDART_INF_F;
    int   bi = K;
    const float4* CB4 = (const float4*)CB;

    if (cnt <= CAP){
        if (lane < cnt){
            int ci = (int)g_cand[(size_t)row * CAP + lane];
            const float4* C4 = CB4 + (size_t)ci * 64;
            float dt = 0.f;
            #pragma unroll 16
            for (int q = 0; q < 64; q++){
                float4 cv = C4[q];
                float4 zv = zr4[q];
                dt = __fmaf_rn(zv.x, cv.x, dt);
                dt = __fmaf_rn(zv.y, cv.y, dt);
                dt = __fmaf_rn(zv.z, cv.z, dt);
                dt = __fmaf_rn(zv.w, cv.w, dt);
            }
            bs = __fmaf_rn(-2.0f, dt, __fadd_rn(zn, g_cnorm[ci]));
            bi = ci;
        }
    } else {
        // overflow fallback: full scan, 32 codes per lane
        for (int j = 0; j < 32; j++){
            int ci = j * 32 + lane;
            const float4* C4 = CB4 + (size_t)ci * 64;
            float dt = 0.f;
            #pragma unroll 16
            for (int q = 0; q < 64; q++){
                float4 cv = C4[q];
                float4 zv = zr4[q];
                dt = __fmaf_rn(zv.x, cv.x, dt);
                dt = __fmaf_rn(zv.y, cv.y, dt);
                dt = __fmaf_rn(zv.z, cv.z, dt);
                dt = __fmaf_rn(zv.w, cv.w, dt);
            }
            float s = __fmaf_rn(-2.0f, dt, __fadd_rn(zn, g_cnorm[ci]));
            if (s < bs || (s == bs && ci < bi)){ bs = s; bi = ci; }
        }
    }

    // lexicographic (score, index) min across warp
    #pragma unroll
    for (int off = 16; off; off >>= 1){
        float s2 = __shfl_xor_sync(0xffffffffu, bs, off);
        int   i2 = __shfl_xor_sync(0xffffffffu, bi, off);
        if (s2 < bs || (s2 == bs && i2 < bi)){ bs = s2; bi = i2; }
    }

    // fused gather: z_q_st output + loss partial
    const float4* C4b = CB4 + (size_t)bi * 64;
    float lsum = 0.f;
    #pragma unroll
    for (int q = 0; q < 2; q++){
        int j = lane + 32 * q;
        float4 z = zr4[j];
        float4 qv = C4b[j];
        float d0 = __fsub_rn(qv.x, z.x);
        float d1 = __fsub_rn(qv.y, z.y);
        float d2 = __fsub_rn(qv.z, z.z);
        float d3 = __fsub_rn(qv.w, z.w);
        float4 o;
        o.x = __fadd_rn(z.x, d0);
        o.y = __fadd_rn(z.y, d1);
        o.z = __fadd_rn(z.z, d2);
        o.w = __fadd_rn(z.w, d3);
        Oz[(size_t)row * 64 + j] = o;
        lsum += d0 * d0 + d1 * d1 + d2 * d2 + d3 * d3;
    }
    #pragma unroll
    for (int off = 16; off; off >>= 1)
        lsum += __shfl_xor_sync(0xffffffffu, lsum, off);
    if (lane == 0){
        wsum[w] = lsum;
        out_idx[row] = (float)bi;
    }
    __syncthreads();
    if (threadIdx.x == 0){
        float bsum = 0.f;
        #pragma unroll
        for (int i = 0; i < 8; i++) bsum += wsum[i];
        atomicAdd(&g_loss_sum, (double)bsum);
    }
}

// ---------------------------------------------------------------------------
__global__ void k_loss(float* __restrict__ out_loss, int n_total){
    double m  = g_loss_sum / (double)n_total;
    float  cb = (float)m;
    out_loss[0] = __fadd_rn(cb, __fmul_rn(0.25f, cb));
}

// ---------------------------------------------------------------------------
extern "C" void kernel_launch(void* const* d_in, const int* in_sizes, int n_in,
                              void* d_out, int out_size)
{
    const float* Z  = (const float*)d_in[0];
    const float* CB = (const float*)d_in[1];
    float* out = (float*)d_out;
    const int n_z = in_sizes[0];      // 16777216
    const int N   = n_z >> 8;         // 65536 rows

    k_setup<<<128, 256>>>(CB);

    cudaFuncSetAttribute(k_gemm, cudaFuncAttributeMaxDynamicSharedMemorySize, GSMEM);
    k_gemm<<<N / GM, 256, GSMEM>>>(Z);

    // out layout: [ z_q_st (n_z) | vq_loss (1) | indices (N) ]
    k_rescore<<<N / 8, 256>>>(Z, CB, (float4*)out, out + n_z + 1);

    k_loss<<<1, 1>>>(out + n_z, n_z);
}